// round 3
// baseline (speedup 1.0000x reference)
#include <cuda_runtime.h>
#include <cstdint>

#define DEV __device__ __forceinline__
typedef unsigned long long u64;

// ---------- packed f32x2 helpers (sm_103a) ----------
DEV u64 ffma2(u64 a, u64 b, u64 c){ u64 d; asm("fma.rn.f32x2 %0, %1, %2, %3;" : "=l"(d) : "l"(a), "l"(b), "l"(c)); return d; }
DEV u64 fmul2(u64 a, u64 b){ u64 d; asm("mul.rn.f32x2 %0, %1, %2;" : "=l"(d) : "l"(a), "l"(b)); return d; }
DEV u64 fadd2(u64 a, u64 b){ u64 d; asm("add.rn.f32x2 %0, %1, %2;" : "=l"(d) : "l"(a), "l"(b)); return d; }
DEV u64 pack2(float lo, float hi){ u64 r; asm("mov.b64 %0, {%1,%2};" : "=l"(r) : "f"(lo), "f"(hi)); return r; }
DEV float2 unpack2(u64 v){ float2 r; asm("mov.b64 {%0,%1}, %2;" : "=f"(r.x), "=f"(r.y) : "l"(v)); return r; }

// dot of 32-elem packed activation (16 x u64) with 32-float smem row (16B aligned)
DEV float dot32s(const u64* a, const float* __restrict__ w){
  u64 acc0 = 0ULL, acc1 = 0ULL;
  const ulonglong2* wp = (const ulonglong2*)w;
  #pragma unroll
  for (int i = 0; i < 8; i++){
    ulonglong2 wv = wp[i];
    acc0 = ffma2(a[2*i],   wv.x, acc0);
    acc1 = ffma2(a[2*i+1], wv.y, acc1);
  }
  float2 f = unpack2(fadd2(acc0, acc1));
  return f.x + f.y;
}

DEV float leakyf(float z){ return fmaxf(z, 0.3f*z); }
DEV float geluf(float z){ return 0.5f*z*(1.0f + erff(z*0.70710678118654752440f)); }

// ---------- problem constants ----------
constexpr int   Bc = 2, Hc = 512, Wcn = 512, Cc = 32, HIDc = 128;
constexpr float SCALEc = 0.17677669529663688f;   // 32^-0.5
constexpr float EPSc = 1e-3f;

// scratch (device globals: allocation-free)
__device__ float g_h [(size_t)Bc*Hc*Wcn*HIDc];   // 256 MB
__device__ float g_x2[(size_t)Bc*Hc*Wcn*Cc];     // 64 MB

// ======================= K1: LN1 + window attention + proj + residual + LN2 + W1/GELU =======================
constexpr int K1_SMEM_FLOATS = 1024 + 2048 + 1024 + 4096 + 384 + 240 + 4*4096; // 25200 floats = 100.8 KB

__global__ void __launch_bounds__(256, 2) k1_attn(
    const float* __restrict__ x,  const float* __restrict__ g1, const float* __restrict__ be1,
    const float* __restrict__ Wq, const float* __restrict__ bq,
    const float* __restrict__ Wkv,const float* __restrict__ bkv,
    const float* __restrict__ btab,
    const float* __restrict__ Wp, const float* __restrict__ bp,
    const float* __restrict__ g2, const float* __restrict__ be2,
    const float* __restrict__ W1, const float* __restrict__ b1m)
{
  extern __shared__ float sm[];
  float* sWq  = sm;                 // [32 out][32 in] transposed
  float* sWkv = sWq  + 1024;        // [64 out][32 in]
  float* sWp  = sWkv + 2048;        // [32][32]
  float* sW1  = sWp  + 1024;        // [128][32]
  float* svec = sW1  + 4096;        // bq(32) bkv(64) bp(32) b1m(128) g1(32) be1(32) g2(32) be2(32)
  float* sbq  = svec;       float* sbkv = svec + 32;  float* sbp  = svec + 96;  float* sb1 = svec + 128;
  float* sg1  = svec + 256; float* sbe1 = svec + 288; float* sg2  = svec + 320; float* sbe2 = svec + 352;
  float* sbt  = svec + 384;         // 225 (padded 240)
  float* skv  = sbt + 240;          // 4 groups * (k 2048 + v 2048)

  const int tid = threadIdx.x;
  for (int i = tid; i < 1024; i += 256) sWq [(i&31)*32 + (i>>5)] = Wq[i];
  for (int i = tid; i < 2048; i += 256) sWkv[(i&63)*32 + (i>>6)] = Wkv[i];
  for (int i = tid; i < 1024; i += 256) sWp [(i&31)*32 + (i>>5)] = Wp[i];
  for (int i = tid; i < 4096; i += 256) sW1 [(i&127)*32 + (i>>7)] = W1[i];
  if (tid < 32)  sbq[tid]  = bq[tid];
  if (tid < 64)  sbkv[tid] = bkv[tid];
  if (tid < 32)  sbp[tid]  = bp[tid];
  if (tid < 128) sb1[tid]  = b1m[tid];
  if (tid < 32){ sg1[tid] = g1[tid]; sbe1[tid] = be1[tid]; sg2[tid] = g2[tid]; sbe2[tid] = be2[tid]; }
  if (tid < 225) sbt[tid] = btab[tid];
  __syncthreads();

  const int g = tid >> 6, t = tid & 63;
  const int w = blockIdx.x*4 + g;
  const int b = w >> 12, rem = w & 4095, wy = rem >> 6, wx = rem & 63;
  const int ty = t >> 3, tx = t & 7;
  const int yy = wy*8 + ty, xx = wx*8 + tx;
  const size_t tok = (size_t)b*262144 + (size_t)yy*512 + xx;
  const float* xrow = x + tok*32;

  // ---- LN1 ----
  float v[32];
  #pragma unroll
  for (int i = 0; i < 8; i++){
    float4 r = *(const float4*)(xrow + 4*i);
    v[4*i] = r.x; v[4*i+1] = r.y; v[4*i+2] = r.z; v[4*i+3] = r.w;
  }
  float mu = 0.f;
  #pragma unroll
  for (int c = 0; c < 32; c++) mu += v[c];
  mu *= (1.f/32.f);
  float var = 0.f;
  #pragma unroll
  for (int c = 0; c < 32; c++){ float d = v[c]-mu; var += d*d; }
  var *= (1.f/32.f);
  float rs = rsqrtf(var + EPSc);
  u64 xu[16];
  #pragma unroll
  for (int i = 0; i < 16; i++){
    float a0 = (v[2*i]  -mu)*rs*sg1[2*i]   + sbe1[2*i];
    float a1 = (v[2*i+1]-mu)*rs*sg1[2*i+1] + sbe1[2*i+1];
    xu[i] = pack2(a0, a1);
  }

  // ---- q = leaky(xn @ Wq + bq) * scale ----
  u64 qu[16];
  #pragma unroll 2
  for (int i = 0; i < 16; i++){
    float a0 = leakyf(dot32s(xu, sWq + (2*i  )*32) + sbq[2*i  ]) * SCALEc;
    float a1 = leakyf(dot32s(xu, sWq + (2*i+1)*32) + sbq[2*i+1]) * SCALEc;
    qu[i] = pack2(a0, a1);
  }

  // ---- k,v = leaky(xn @ Wkv + bkv) -> smem ----
  float* kbuf = skv + g*4096;
  float* vbuf = kbuf + 2048;
  #pragma unroll 2
  for (int j = 0; j < 64; j += 4){
    float a0 = leakyf(dot32s(xu, sWkv + (j  )*32) + sbkv[j  ]);
    float a1 = leakyf(dot32s(xu, sWkv + (j+1)*32) + sbkv[j+1]);
    float a2 = leakyf(dot32s(xu, sWkv + (j+2)*32) + sbkv[j+2]);
    float a3 = leakyf(dot32s(xu, sWkv + (j+3)*32) + sbkv[j+3]);
    float4 f = make_float4(a0, a1, a2, a3);
    if (j < 32) *(float4*)(kbuf + t*32 + j)      = f;
    else        *(float4*)(vbuf + t*32 + (j-32)) = f;
  }
  __syncthreads();

  // ---- online-softmax attention ----
  u64 Ou[16];
  #pragma unroll
  for (int i = 0; i < 16; i++) Ou[i] = 0ULL;
  float mrun = -3.0e38f, l = 0.f;
  #pragma unroll 2
  for (int m = 0; m < 64; m++){
    float s = dot32s(qu, kbuf + m*32);
    s += sbt[(tx - (m&7) + 7)*15 + (ty - (m>>3) + 7)];
    float nm = fmaxf(mrun, s);
    if (nm > mrun){
      float f = __expf(mrun - nm);
      u64 ff = pack2(f, f);
      l *= f;
      #pragma unroll
      for (int i = 0; i < 16; i++) Ou[i] = fmul2(Ou[i], ff);
      mrun = nm;
    }
    float p = __expf(s - mrun);
    l += p;
    u64 pp = pack2(p, p);
    const ulonglong2* vp = (const ulonglong2*)(vbuf + m*32);
    #pragma unroll
    for (int i = 0; i < 8; i++){
      ulonglong2 vv = vp[i];
      Ou[2*i]   = ffma2(pp, vv.x, Ou[2*i]);
      Ou[2*i+1] = ffma2(pp, vv.y, Ou[2*i+1]);
    }
  }
  {
    float linv = 1.f / l;
    u64 li = pack2(linv, linv);
    #pragma unroll
    for (int i = 0; i < 16; i++) Ou[i] = fmul2(Ou[i], li);
  }

  // ---- proj + shortcut residual -> x2 ----
  float x2r[32];
  #pragma unroll 2
  for (int j = 0; j < 32; j++) x2r[j] = dot32s(Ou, sWp + j*32) + sbp[j];
  float* x2g = g_x2 + tok*32;
  #pragma unroll
  for (int i = 0; i < 8; i++){
    float4 sc = *(const float4*)(xrow + 4*i);
    x2r[4*i]   += sc.x; x2r[4*i+1] += sc.y; x2r[4*i+2] += sc.z; x2r[4*i+3] += sc.w;
    *(float4*)(x2g + 4*i) = make_float4(x2r[4*i], x2r[4*i+1], x2r[4*i+2], x2r[4*i+3]);
  }

  // ---- LN2 ----
  mu = 0.f;
  #pragma unroll
  for (int c = 0; c < 32; c++) mu += x2r[c];
  mu *= (1.f/32.f);
  var = 0.f;
  #pragma unroll
  for (int c = 0; c < 32; c++){ float d = x2r[c]-mu; var += d*d; }
  var *= (1.f/32.f);
  rs = rsqrtf(var + EPSc);
  u64 yu[16];
  #pragma unroll
  for (int i = 0; i < 16; i++){
    float a0 = (x2r[2*i]  -mu)*rs*sg2[2*i]   + sbe2[2*i];
    float a1 = (x2r[2*i+1]-mu)*rs*sg2[2*i+1] + sbe2[2*i+1];
    yu[i] = pack2(a0, a1);
  }

  // ---- h = gelu(y @ W1 + b1) -> global scratch ----
  float* hg = g_h + tok*128;
  #pragma unroll 1
  for (int j = 0; j < 128; j += 4){
    float a0 = geluf(dot32s(yu, sW1 + (j  )*32) + sb1[j  ]);
    float a1 = geluf(dot32s(yu, sW1 + (j+1)*32) + sb1[j+1]);
    float a2 = geluf(dot32s(yu, sW1 + (j+2)*32) + sb1[j+2]);
    float a3 = geluf(dot32s(yu, sW1 + (j+3)*32) + sb1[j+3]);
    *(float4*)(hg + j) = make_float4(a0, a1, a2, a3);
  }
}

// ======================= K2: depthwise 3x3 conv + GELU + W2 GEMM + residual =======================
constexpr int K2_SMEM_FLOATS = 4096 + 1152 + 128 + 32 + 64*132;  // 13856 floats = 55.4 KB

__global__ void __launch_bounds__(256) k2_leff(
    const float* __restrict__ dwk, const float* __restrict__ dwb,
    const float* __restrict__ W2,  const float* __restrict__ b2m,
    float* __restrict__ out)
{
  extern __shared__ float sm[];
  float* sW2  = sm;            // [128 k][32 c]
  float* sdw  = sW2 + 4096;    // [9 tap][128 ch]
  float* sdwb = sdw + 1152;    // 128
  float* sb2  = sdwb + 128;    // 32
  float* shc  = sb2 + 32;      // 64 pixels x 132 (padded)

  const int tid = threadIdx.x;
  for (int i = tid; i < 4096; i += 256) sW2[i] = W2[i];
  for (int i = tid; i < 1152; i += 256) sdw[i] = dwk[i];
  if (tid < 128) sdwb[tid] = dwb[tid];
  if (tid < 32)  sb2[tid]  = b2m[tid];
  __syncthreads();

  const int blk = blockIdx.x;
  const int b = blk >> 12, rem = blk & 4095;
  const int ty0 = (rem >> 6)*8, tx0 = (rem & 63)*8;
  const int p = tid >> 2, gq = tid & 3;
  const int py = p >> 3, px = p & 7;
  const int y = ty0 + py, xc = tx0 + px;
  const int cb = gq*32;

  // ---- phase A: depthwise conv (+bias, gelu) for 32 channels of this pixel ----
  u64 acc[16];
  #pragma unroll
  for (int i = 0; i < 16; i++) acc[i] = pack2(sdwb[cb+2*i], sdwb[cb+2*i+1]);
  #pragma unroll
  for (int ky = 0; ky < 3; ky++){
    int ny = y + ky - 1;
    if ((unsigned)ny >= 512u) continue;
    #pragma unroll
    for (int kx = 0; kx < 3; kx++){
      int nx = xc + kx - 1;
      if ((unsigned)nx >= 512u) continue;
      const ulonglong2* hp = (const ulonglong2*)(g_h + ((size_t)b*262144 + (size_t)ny*512 + nx)*128 + cb);
      const ulonglong2* wp = (const ulonglong2*)(sdw + (ky*3+kx)*128 + cb);
      #pragma unroll
      for (int i = 0; i < 8; i++){
        ulonglong2 hv = hp[i]; ulonglong2 wv = wp[i];
        acc[2*i]   = ffma2(hv.x, wv.x, acc[2*i]);
        acc[2*i+1] = ffma2(hv.y, wv.y, acc[2*i+1]);
      }
    }
  }
  float* hrow = shc + p*132;
  #pragma unroll
  for (int i = 0; i < 16; i++){
    float2 f = unpack2(acc[i]);
    f.x = geluf(f.x); f.y = geluf(f.y);
    *(float2*)(hrow + cb + 2*i) = f;
  }
  __syncthreads();

  // ---- phase B: out[c0..c0+8) = hconv @ W2 + b2m + x2 ----
  const int c0 = gq*8;
  u64 a2[4];
  #pragma unroll
  for (int i = 0; i < 4; i++) a2[i] = pack2(sb2[c0+2*i], sb2[c0+2*i+1]);
  #pragma unroll 4
  for (int k = 0; k < 128; k += 4){
    float4 hv = *(const float4*)(hrow + k);
    #pragma unroll
    for (int kk = 0; kk < 4; kk++){
      u64 hh = pack2((&hv.x)[kk], (&hv.x)[kk]);
      const ulonglong2* wr = (const ulonglong2*)(sW2 + (k+kk)*32 + c0);
      ulonglong2 wa = wr[0], wb = wr[1];
      a2[0] = ffma2(hh, wa.x, a2[0]);
      a2[1] = ffma2(hh, wa.y, a2[1]);
      a2[2] = ffma2(hh, wb.x, a2[2]);
      a2[3] = ffma2(hh, wb.y, a2[3]);
    }
  }
  const size_t pbase = ((size_t)b*262144 + (size_t)y*512 + xc)*32 + c0;
  const float* x2p = g_x2 + pbase;
  float2 f0 = unpack2(a2[0]), f1 = unpack2(a2[1]), f2 = unpack2(a2[2]), f3 = unpack2(a2[3]);
  float4 xa = *(const float4*)(x2p);
  float4 xb = *(const float4*)(x2p + 4);
  *(float4*)(out + pbase)     = make_float4(f0.x+xa.x, f0.y+xa.y, f1.x+xa.z, f1.y+xa.w);
  *(float4*)(out + pbase + 4) = make_float4(f2.x+xb.x, f2.y+xb.y, f3.x+xb.z, f3.y+xb.w);
}

// ======================= launch =======================
extern "C" void kernel_launch(void* const* d_in, const int* in_sizes, int n_in,
                              void* d_out, int out_size)
{
  (void)in_sizes; (void)n_in; (void)out_size;
  const float* x    = (const float*)d_in[0];
  const float* g1   = (const float*)d_in[1];
  const float* be1  = (const float*)d_in[2];
  const float* Wq   = (const float*)d_in[3];
  const float* bq   = (const float*)d_in[4];
  const float* Wkv  = (const float*)d_in[5];
  const float* bkv  = (const float*)d_in[6];
  const float* btab = (const float*)d_in[7];
  const float* Wp   = (const float*)d_in[8];
  const float* bp   = (const float*)d_in[9];
  const float* g2   = (const float*)d_in[10];
  const float* be2  = (const float*)d_in[11];
  const float* W1   = (const float*)d_in[12];
  const float* b1m  = (const float*)d_in[13];
  const float* dwk  = (const float*)d_in[14];
  const float* dwb  = (const float*)d_in[15];
  const float* W2   = (const float*)d_in[16];
  const float* b2m  = (const float*)d_in[17];
  // d_in[18] = rel_idx (bias index computed analytically in-kernel)
  float* out = (float*)d_out;

  cudaFuncSetAttribute(k1_attn, cudaFuncAttributeMaxDynamicSharedMemorySize, K1_SMEM_FLOATS*4);
  cudaFuncSetAttribute(k2_leff, cudaFuncAttributeMaxDynamicSharedMemorySize, K2_SMEM_FLOATS*4);

  k1_attn<<<2048, 256, K1_SMEM_FLOATS*4>>>(x, g1, be1, Wq, bq, Wkv, bkv, btab, Wp, bp, g2, be2, W1, b1m);
  k2_leff<<<8192, 256, K2_SMEM_FLOATS*4>>>(dwk, dwb, W2, b2m, out);
}

// round 5
// speedup vs baseline: 1.3211x; 1.3211x over previous
#include <cuda_runtime.h>
#include <cstdint>

#define DEV __device__ __forceinline__
typedef unsigned long long u64;

DEV u64 ffma2(u64 a, u64 b, u64 c){ u64 d; asm("fma.rn.f32x2 %0, %1, %2, %3;" : "=l"(d) : "l"(a), "l"(b), "l"(c)); return d; }
DEV u64 fmul2(u64 a, u64 b){ u64 d; asm("mul.rn.f32x2 %0, %1, %2;" : "=l"(d) : "l"(a), "l"(b)); return d; }
DEV u64 fadd2(u64 a, u64 b){ u64 d; asm("add.rn.f32x2 %0, %1, %2;" : "=l"(d) : "l"(a), "l"(b)); return d; }
DEV u64 pack2(float lo, float hi){ u64 r; asm("mov.b64 %0, {%1,%2};" : "=l"(r) : "f"(lo), "f"(hi)); return r; }
DEV float2 unpack2(u64 v){ float2 r; asm("mov.b64 {%0,%1}, %2;" : "=f"(r.x), "=f"(r.y) : "l"(v)); return r; }

DEV float dot32s(const u64* a, const float* __restrict__ w){
  u64 acc0 = 0ULL, acc1 = 0ULL;
  const ulonglong2* wp = (const ulonglong2*)w;
  #pragma unroll
  for (int i = 0; i < 8; i++){
    ulonglong2 wv = wp[i];
    acc0 = ffma2(a[2*i],   wv.x, acc0);
    acc1 = ffma2(a[2*i+1], wv.y, acc1);
  }
  float2 f = unpack2(fadd2(acc0, acc1));
  return f.x + f.y;
}

DEV float leakyf(float z){ return fmaxf(z, 0.3f*z); }
DEV float geluf(float z){ return 0.5f*z*(1.0f + erff(z*0.70710678118654752440f)); }

constexpr float SCALEc = 0.17677669529663688f;
constexpr float EPSc = 1e-3f;

__device__ float g_h [(size_t)2*512*512*128];   // 256 MB
__device__ float g_x2[(size_t)2*512*512*32];    // 64 MB

// ======================= K1 =======================
constexpr int RS = 36;                  // padded token-row stride
constexpr int K1_SMF = 8816 + 4*4608;   // 27248 floats = 108,992 B

__global__ void __launch_bounds__(256, 2) k1_attn(
    const float* __restrict__ x,  const float* __restrict__ g1, const float* __restrict__ be1,
    const float* __restrict__ Wq, const float* __restrict__ bq,
    const float* __restrict__ Wkv,const float* __restrict__ bkv,
    const float* __restrict__ btab,
    const float* __restrict__ Wp, const float* __restrict__ bp,
    const float* __restrict__ g2, const float* __restrict__ be2,
    const float* __restrict__ W1, const float* __restrict__ b1m)
{
  extern __shared__ float sm[];
  float* sWq  = sm;            // [32 out][32 in] transposed
  float* sWkv = sm + 1024;     // [64][32]
  float* sWp  = sm + 3072;     // [32][32]
  float* sW1  = sm + 4096;     // [128][32]
  float* svec = sm + 8192;
  float* sbt  = sm + 8576;     // 225
  float* rg   = sm + 8816;     // 4 groups x (A 2304 | B 2304)
  float* sbq  = svec;       float* sbkv = svec + 32;  float* sbp  = svec + 96;  float* sb1 = svec + 128;
  float* sg1  = svec + 256; float* sbe1 = svec + 288; float* sg2  = svec + 320; float* sbe2 = svec + 352;

  const int tid = threadIdx.x;
  for (int i = tid; i < 1024; i += 256) sWq [(i&31)*32 + (i>>5)]  = Wq[i];
  for (int i = tid; i < 2048; i += 256) sWkv[(i&63)*32 + (i>>6)]  = Wkv[i];
  for (int i = tid; i < 1024; i += 256) sWp [(i&31)*32 + (i>>5)]  = Wp[i];
  for (int i = tid; i < 4096; i += 256) sW1 [(i&127)*32 + (i>>7)] = W1[i];
  if (tid < 32)  sbq[tid]  = bq[tid];
  if (tid < 64)  sbkv[tid] = bkv[tid];
  if (tid < 32)  sbp[tid]  = bp[tid];
  if (tid < 128) sb1[tid]  = b1m[tid];
  if (tid < 32){ sg1[tid] = g1[tid]; sbe1[tid] = be1[tid]; sg2[tid] = g2[tid]; sbe2[tid] = be2[tid]; }
  if (tid < 225) sbt[tid] = btab[tid];

  // coop load x -> A regions (coalesced global, conflict-free smem)
  #pragma unroll
  for (int i = 0; i < 8; i++){
    int q = tid + i*256; int gg = q>>9; int tt = (q>>3)&63; int j4 = q&7;
    int w = blockIdx.x*4 + gg; int bb = w>>12, rem = w&4095, wy = rem>>6, wx = rem&63;
    size_t tok = (size_t)bb*262144 + (size_t)(wy*8 + (tt>>3))*512 + wx*8 + (tt&7);
    *(float4*)(rg + gg*4608 + tt*RS + j4*4) = *(const float4*)(x + tok*32 + j4*4);
  }
  __syncthreads();

  const int g = tid >> 6, t = tid & 63;
  const int ty = t >> 3, tx = t & 7;
  float* A  = rg + g*4608;
  float* Bb = A + 2304;
  const int bbias = (tx + 7)*15 + (ty + 7);

  // LN1 from staged A
  float vv[32];
  #pragma unroll
  for (int i = 0; i < 8; i++){
    float4 r = *(const float4*)(A + t*RS + 4*i);
    vv[4*i] = r.x; vv[4*i+1] = r.y; vv[4*i+2] = r.z; vv[4*i+3] = r.w;
  }
  float mu = 0.f;
  #pragma unroll
  for (int c = 0; c < 32; c++) mu += vv[c];
  mu *= (1.f/32.f);
  float var = 0.f;
  #pragma unroll
  for (int c = 0; c < 32; c++){ float d = vv[c]-mu; var += d*d; }
  var *= (1.f/32.f);
  float rs = rsqrtf(var + EPSc);
  u64 xu[16];
  #pragma unroll
  for (int i = 0; i < 16; i++){
    float a0 = (vv[2*i]  -mu)*rs*sg1[2*i]   + sbe1[2*i];
    float a1 = (vv[2*i+1]-mu)*rs*sg1[2*i+1] + sbe1[2*i+1];
    xu[i] = pack2(a0, a1);
  }

  // q
  u64 qu[16];
  #pragma unroll
  for (int i = 0; i < 16; i++){
    float a0 = leakyf(dot32s(xu, sWq + (2*i  )*32) + sbq[2*i  ]) * SCALEc;
    float a1 = leakyf(dot32s(xu, sWq + (2*i+1)*32) + sbq[2*i+1]) * SCALEc;
    qu[i] = pack2(a0, a1);
  }
  // k -> B (stride 36, conflict-free)
  #pragma unroll 2
  for (int j = 0; j < 32; j += 4){
    float a0 = leakyf(dot32s(xu, sWkv + (j  )*32) + sbkv[j  ]);
    float a1 = leakyf(dot32s(xu, sWkv + (j+1)*32) + sbkv[j+1]);
    float a2 = leakyf(dot32s(xu, sWkv + (j+2)*32) + sbkv[j+2]);
    float a3 = leakyf(dot32s(xu, sWkv + (j+3)*32) + sbkv[j+3]);
    *(float4*)(Bb + t*RS + j) = make_float4(a0, a1, a2, a3);
  }
  // v -> A (own row already consumed)
  #pragma unroll 2
  for (int j = 0; j < 32; j += 4){
    float a0 = leakyf(dot32s(xu, sWkv + (32+j  )*32) + sbkv[32+j  ]);
    float a1 = leakyf(dot32s(xu, sWkv + (32+j+1)*32) + sbkv[32+j+1]);
    float a2 = leakyf(dot32s(xu, sWkv + (32+j+2)*32) + sbkv[32+j+2]);
    float a3 = leakyf(dot32s(xu, sWkv + (32+j+3)*32) + sbkv[32+j+3]);
    *(float4*)(A + t*RS + j) = make_float4(a0, a1, a2, a3);
  }
  __syncthreads();

  // pass 1: scores into regs, track max
  float s[64];
  float mx = -3.0e38f;
  #pragma unroll
  for (int m = 0; m < 64; m++){
    float sc = dot32s(qu, Bb + m*RS) + sbt[bbias - ((m&7)*15 + (m>>3))];
    s[m] = sc; mx = fmaxf(mx, sc);
  }
  __syncthreads();   // all k reads done -> B reusable

  // coop reload x -> B (residual), overlapped with softmax/PV math
  #pragma unroll
  for (int i = 0; i < 8; i++){
    int q = tid + i*256; int gg = q>>9; int tt = (q>>3)&63; int j4 = q&7;
    int w = blockIdx.x*4 + gg; int bb = w>>12, rem = w&4095, wy = rem>>6, wx = rem&63;
    size_t tok = (size_t)bb*262144 + (size_t)(wy*8 + (tt>>3))*512 + wx*8 + (tt&7);
    *(float4*)(rg + gg*4608 + 2304 + tt*RS + j4*4) = *(const float4*)(x + tok*32 + j4*4);
  }

  float l = 0.f;
  #pragma unroll
  for (int m = 0; m < 64; m++){ float p = __expf(s[m]-mx); l += p; s[m] = p; }

  u64 Ou[16];
  #pragma unroll
  for (int i = 0; i < 16; i++) Ou[i] = 0ULL;
  #pragma unroll
  for (int m = 0; m < 64; m++){
    u64 pp = pack2(s[m], s[m]);
    const ulonglong2* vp = (const ulonglong2*)(A + m*RS);
    #pragma unroll
    for (int i = 0; i < 8; i++){
      ulonglong2 vq = vp[i];
      Ou[2*i]   = ffma2(pp, vq.x, Ou[2*i]);
      Ou[2*i+1] = ffma2(pp, vq.y, Ou[2*i+1]);
    }
  }
  {
    float linv = 1.f / l;
    u64 li = pack2(linv, linv);
    #pragma unroll
    for (int i = 0; i < 16; i++) Ou[i] = fmul2(Ou[i], li);
  }
  __syncthreads();  // PV done (A free), x reload visible

  // proj + residual
  float x2r[32];
  #pragma unroll 2
  for (int j = 0; j < 32; j++) x2r[j] = dot32s(Ou, sWp + j*32) + sbp[j];
  #pragma unroll
  for (int i = 0; i < 8; i++){
    float4 r = *(const float4*)(Bb + t*RS + 4*i);
    x2r[4*i] += r.x; x2r[4*i+1] += r.y; x2r[4*i+2] += r.z; x2r[4*i+3] += r.w;
  }
  #pragma unroll
  for (int i = 0; i < 8; i++)
    *(float4*)(A + t*RS + 4*i) = make_float4(x2r[4*i], x2r[4*i+1], x2r[4*i+2], x2r[4*i+3]);

  // LN2 in regs
  mu = 0.f;
  #pragma unroll
  for (int c = 0; c < 32; c++) mu += x2r[c];
  mu *= (1.f/32.f);
  var = 0.f;
  #pragma unroll
  for (int c = 0; c < 32; c++){ float d = x2r[c]-mu; var += d*d; }
  var *= (1.f/32.f);
  rs = rsqrtf(var + EPSc);
  u64 yu[16];
  #pragma unroll
  for (int i = 0; i < 16; i++){
    float a0 = (x2r[2*i]  -mu)*rs*sg2[2*i]   + sbe2[2*i];
    float a1 = (x2r[2*i+1]-mu)*rs*sg2[2*i+1] + sbe2[2*i+1];
    yu[i] = pack2(a0, a1);
  }
  __syncthreads();

  // coop write x2 (coalesced)
  #pragma unroll
  for (int i = 0; i < 8; i++){
    int q = tid + i*256; int gg = q>>9; int tt = (q>>3)&63; int j4 = q&7;
    int w = blockIdx.x*4 + gg; int bb = w>>12, rem = w&4095, wy = rem>>6, wx = rem&63;
    size_t tok = (size_t)bb*262144 + (size_t)(wy*8 + (tt>>3))*512 + wx*8 + (tt&7);
    *(float4*)(g_x2 + tok*32 + j4*4) = *(const float4*)(rg + gg*4608 + tt*RS + j4*4);
  }
  __syncthreads();

  // h = gelu(y @ W1 + b1), staged + coalesced, 4 quarters of 32 channels
  #pragma unroll 1
  for (int qt = 0; qt < 4; qt++){
    float hq[32];
    #pragma unroll 2
    for (int jj = 0; jj < 32; jj += 4){
      int j = qt*32 + jj;
      hq[jj  ] = geluf(dot32s(yu, sW1 + (j  )*32) + sb1[j  ]);
      hq[jj+1] = geluf(dot32s(yu, sW1 + (j+1)*32) + sb1[j+1]);
      hq[jj+2] = geluf(dot32s(yu, sW1 + (j+2)*32) + sb1[j+2]);
      hq[jj+3] = geluf(dot32s(yu, sW1 + (j+3)*32) + sb1[j+3]);
    }
    #pragma unroll
    for (int i = 0; i < 8; i++)
      *(float4*)(A + t*RS + 4*i) = make_float4(hq[4*i], hq[4*i+1], hq[4*i+2], hq[4*i+3]);
    __syncthreads();
    #pragma unroll
    for (int i = 0; i < 8; i++){
      int q = tid + i*256; int gg = q>>9; int tt = (q>>3)&63; int j4 = q&7;
      int w = blockIdx.x*4 + gg; int bb = w>>12, rem = w&4095, wy = rem>>6, wx = rem&63;
      size_t tok = (size_t)bb*262144 + (size_t)(wy*8 + (tt>>3))*512 + wx*8 + (tt&7);
      *(float4*)(g_h + tok*128 + qt*32 + j4*4) = *(const float4*)(rg + gg*4608 + tt*RS + j4*4);
    }
    __syncthreads();
  }
}

// ======================= K2 =======================
// 8x8 pixel tile/block; 10x10x128 halo staged in smem.
// tile layout: pixel stride 164 floats, channel-group stride 40 -> conflict-free.
constexpr int PST = 164;
constexpr int K2_SMF = 5768 + 100*PST;   // 22168 floats = 88,672 B

__global__ void __launch_bounds__(256, 2) k2_leff(
    const float* __restrict__ dwk, const float* __restrict__ dwb,
    const float* __restrict__ W2,  const float* __restrict__ b2m,
    float* __restrict__ out)
{
  extern __shared__ float sm[];
  float* sW2  = sm;            // [128 k][32 c]
  float* sdw  = sm + 4096;     // [9 tap][4 grp x 40 + pad] stride 168
  float* sdwb = sm + 5608;     // 128
  float* sb2  = sm + 5736;     // 32
  float* st   = sm + 5768;     // 100 x 164

  const int tid = threadIdx.x;
  for (int i = tid; i < 4096; i += 256) sW2[i] = W2[i];
  for (int i = tid; i < 1152; i += 256){
    int tap = i >> 7, c = i & 127;
    sdw[tap*168 + 40*(c>>5) + (c&31)] = dwk[i];
  }
  if (tid < 128) sdwb[tid] = dwb[tid];
  if (tid < 32)  sb2[tid]  = b2m[tid];

  const int blk = blockIdx.x, b = blk >> 12, rem = blk & 4095;
  const int y0 = (rem >> 6)*8, x0 = (rem & 63)*8;

  // stage halo: warp per pixel vector, coalesced 512B
  const int wid = tid >> 5, lane = tid & 31;
  const int coff = 40*(lane>>3) + 4*(lane&7);
  for (int vid = wid; vid < 100; vid += 8){
    int r = vid/10, c = vid - r*10;
    int hy = y0 + r - 1, hx = x0 + c - 1;
    float4 val = make_float4(0.f, 0.f, 0.f, 0.f);
    if ((unsigned)hy < 512u && (unsigned)hx < 512u)
      val = *(const float4*)(g_h + ((size_t)b*262144 + (size_t)hy*512 + hx)*128 + lane*4);
    *(float4*)(st + vid*PST + coff) = val;
  }
  __syncthreads();

  const int p = tid >> 2, gq = tid & 3;
  const int py = p >> 3, px = p & 7;
  const int cv = (py+1)*10 + (px+1);
  const int cb = gq*40;
  const int cw = gq*32;

  // depthwise conv from smem (zero halo handles SAME padding)
  u64 acc[16];
  #pragma unroll
  for (int i = 0; i < 16; i++) acc[i] = pack2(sdwb[cw+2*i], sdwb[cw+2*i+1]);
  #pragma unroll
  for (int ky = 0; ky < 3; ky++){
    #pragma unroll
    for (int kx = 0; kx < 3; kx++){
      const ulonglong2* hp = (const ulonglong2*)(st + (cv + (ky-1)*10 + (kx-1))*PST + cb);
      const ulonglong2* wp = (const ulonglong2*)(sdw + (ky*3+kx)*168 + cb);
      #pragma unroll
      for (int i = 0; i < 8; i++){
        ulonglong2 hv = hp[i], wv = wp[i];
        acc[2*i]   = ffma2(hv.x, wv.x, acc[2*i]);
        acc[2*i+1] = ffma2(hv.y, wv.y, acc[2*i+1]);
      }
    }
  }
  __syncthreads();   // conv reads complete before in-place overwrite

  float hg[32];
  #pragma unroll
  for (int i = 0; i < 16; i++){
    float2 f = unpack2(acc[i]);
    hg[2*i] = geluf(f.x); hg[2*i+1] = geluf(f.y);
  }
  #pragma unroll
  for (int i = 0; i < 8; i++)
    *(float4*)(st + cv*PST + cb + 4*i) = make_float4(hg[4*i], hg[4*i+1], hg[4*i+2], hg[4*i+3]);
  __syncthreads();

  // GEMM 128 -> 8 outs/thread + bias + x2 residual
  const int c0 = gq*8;
  u64 a2[4];
  #pragma unroll
  for (int i = 0; i < 4; i++) a2[i] = pack2(sb2[c0+2*i], sb2[c0+2*i+1]);
  const float* hrow = st + cv*PST;
  #pragma unroll
  for (int kg = 0; kg < 4; kg++){
    const float* hp = hrow + kg*40;
    #pragma unroll 4
    for (int j = 0; j < 32; j += 4){
      float4 hv = *(const float4*)(hp + j);
      #pragma unroll
      for (int kk = 0; kk < 4; kk++){
        float hvv = (&hv.x)[kk];
        u64 hh = pack2(hvv, hvv);
        const ulonglong2* wr = (const ulonglong2*)(sW2 + (kg*32 + j + kk)*32 + c0);
        ulonglong2 wa = wr[0], wb = wr[1];
        a2[0] = ffma2(hh, wa.x, a2[0]);
        a2[1] = ffma2(hh, wa.y, a2[1]);
        a2[2] = ffma2(hh, wb.x, a2[2]);
        a2[3] = ffma2(hh, wb.y, a2[3]);
      }
    }
  }
  const int yy = y0 + py, xx = x0 + px;
  const size_t pbase = ((size_t)b*262144 + (size_t)yy*512 + xx)*32 + c0;
  const float* x2p = g_x2 + pbase;
  float2 f0 = unpack2(a2[0]), f1 = unpack2(a2[1]), f2 = unpack2(a2[2]), f3 = unpack2(a2[3]);
  float4 xa = *(const float4*)(x2p);
  float4 xb = *(const float4*)(x2p + 4);
  *(float4*)(out + pbase)     = make_float4(f0.x+xa.x, f0.y+xa.y, f1.x+xa.z, f1.y+xa.w);
  *(float4*)(out + pbase + 4) = make_float4(f2.x+xb.x, f2.y+xb.y, f3.x+xb.z, f3.y+xb.w);
}

// ======================= launch =======================
extern "C" void kernel_launch(void* const* d_in, const int* in_sizes, int n_in,
                              void* d_out, int out_size)
{
  (void)in_sizes; (void)n_in; (void)out_size;
  const float* x    = (const float*)d_in[0];
  const float* g1   = (const float*)d_in[1];
  const float* be1  = (const float*)d_in[2];
  const float* Wq   = (const float*)d_in[3];
  const float* bq   = (const float*)d_in[4];
  const float* Wkv  = (const float*)d_in[5];
  const float* bkv  = (const float*)d_in[6];
  const float* btab = (const float*)d_in[7];
  const float* Wp   = (const float*)d_in[8];
  const float* bp   = (const float*)d_in[9];
  const float* g2   = (const float*)d_in[10];
  const float* be2  = (const float*)d_in[11];
  const float* W1   = (const float*)d_in[12];
  const float* b1m  = (const float*)d_in[13];
  const float* dwk  = (const float*)d_in[14];
  const float* dwb  = (const float*)d_in[15];
  const float* W2   = (const float*)d_in[16];
  const float* b2m  = (const float*)d_in[17];
  float* out = (float*)d_out;

  cudaFuncSetAttribute(k1_attn, cudaFuncAttributeMaxDynamicSharedMemorySize, K1_SMF*4);
  cudaFuncSetAttribute(k2_leff, cudaFuncAttributeMaxDynamicSharedMemorySize, K2_SMF*4);

  k1_attn<<<2048, 256, K1_SMF*4>>>(x, g1, be1, Wq, bq, Wkv, bkv, btab, Wp, bp, g2, be2, W1, b1m);
  k2_leff<<<8192, 256, K2_SMF*4>>>(dwk, dwb, W2, b2m, out);
}

// round 9
// speedup vs baseline: 1.5684x; 1.1872x over previous
#include <cuda_runtime.h>
#include <cstdint>

#define DEV __device__ __forceinline__
typedef unsigned long long u64;

DEV u64 ffma2(u64 a, u64 b, u64 c){ u64 d; asm("fma.rn.f32x2 %0, %1, %2, %3;" : "=l"(d) : "l"(a), "l"(b), "l"(c)); return d; }
DEV u64 fmul2(u64 a, u64 b){ u64 d; asm("mul.rn.f32x2 %0, %1, %2;" : "=l"(d) : "l"(a), "l"(b)); return d; }
DEV u64 fadd2(u64 a, u64 b){ u64 d; asm("add.rn.f32x2 %0, %1, %2;" : "=l"(d) : "l"(a), "l"(b)); return d; }
DEV u64 pack2(float lo, float hi){ u64 r; asm("mov.b64 %0, {%1,%2};" : "=l"(r) : "f"(lo), "f"(hi)); return r; }
DEV float2 unpack2(u64 v){ float2 r; asm("mov.b64 {%0,%1}, %2;" : "=f"(r.x), "=f"(r.y) : "l"(v)); return r; }

DEV float dot32s(const u64* a, const float* __restrict__ w){
  u64 acc0 = 0ULL, acc1 = 0ULL;
  const ulonglong2* wp = (const ulonglong2*)w;
  #pragma unroll
  for (int i = 0; i < 8; i++){
    ulonglong2 wv = wp[i];
    acc0 = ffma2(a[2*i],   wv.x, acc0);
    acc1 = ffma2(a[2*i+1], wv.y, acc1);
  }
  float2 f = unpack2(fadd2(acc0, acc1));
  return f.x + f.y;
}

DEV float leakyf(float z){ return fmaxf(z, 0.3f*z); }
DEV float geluf(float z){ return 0.5f*z*(1.0f + erff(z*0.70710678118654752440f)); }

constexpr float SCALEc = 0.17677669529663688f;
constexpr float EPSc = 1e-3f;

__device__ float g_h [(size_t)2*512*512*128];   // 256 MB
__device__ float g_x2[(size_t)2*512*512*32];    // 64 MB

// ======================= K1 (unchanged from R5 known-good) =======================
constexpr int RS = 36;
constexpr int K1_SMF = 8816 + 4*4608;

__global__ void __launch_bounds__(256, 2) k1_attn(
    const float* __restrict__ x,  const float* __restrict__ g1, const float* __restrict__ be1,
    const float* __restrict__ Wq, const float* __restrict__ bq,
    const float* __restrict__ Wkv,const float* __restrict__ bkv,
    const float* __restrict__ btab,
    const float* __restrict__ Wp, const float* __restrict__ bp,
    const float* __restrict__ g2, const float* __restrict__ be2,
    const float* __restrict__ W1, const float* __restrict__ b1m)
{
  extern __shared__ float sm[];
  float* sWq  = sm;
  float* sWkv = sm + 1024;
  float* sWp  = sm + 3072;
  float* sW1  = sm + 4096;
  float* svec = sm + 8192;
  float* sbt  = sm + 8576;
  float* rg   = sm + 8816;
  float* sbq  = svec;       float* sbkv = svec + 32;  float* sbp  = svec + 96;  float* sb1 = svec + 128;
  float* sg1  = svec + 256; float* sbe1 = svec + 288; float* sg2  = svec + 320; float* sbe2 = svec + 352;

  const int tid = threadIdx.x;
  for (int i = tid; i < 1024; i += 256) sWq [(i&31)*32 + (i>>5)]  = Wq[i];
  for (int i = tid; i < 2048; i += 256) sWkv[(i&63)*32 + (i>>6)]  = Wkv[i];
  for (int i = tid; i < 1024; i += 256) sWp [(i&31)*32 + (i>>5)]  = Wp[i];
  for (int i = tid; i < 4096; i += 256) sW1 [(i&127)*32 + (i>>7)] = W1[i];
  if (tid < 32)  sbq[tid]  = bq[tid];
  if (tid < 64)  sbkv[tid] = bkv[tid];
  if (tid < 32)  sbp[tid]  = bp[tid];
  if (tid < 128) sb1[tid]  = b1m[tid];
  if (tid < 32){ sg1[tid] = g1[tid]; sbe1[tid] = be1[tid]; sg2[tid] = g2[tid]; sbe2[tid] = be2[tid]; }
  if (tid < 225) sbt[tid] = btab[tid];

  #pragma unroll
  for (int i = 0; i < 8; i++){
    int q = tid + i*256; int gg = q>>9; int tt = (q>>3)&63; int j4 = q&7;
    int w = blockIdx.x*4 + gg; int bb = w>>12, rem = w&4095, wy = rem>>6, wx = rem&63;
    size_t tok = (size_t)bb*262144 + (size_t)(wy*8 + (tt>>3))*512 + wx*8 + (tt&7);
    *(float4*)(rg + gg*4608 + tt*RS + j4*4) = *(const float4*)(x + tok*32 + j4*4);
  }
  __syncthreads();

  const int g = tid >> 6, t = tid & 63;
  const int ty = t >> 3, tx = t & 7;
  float* A  = rg + g*4608;
  float* Bb = A + 2304;
  const int bbias = (tx + 7)*15 + (ty + 7);

  float vv[32];
  #pragma unroll
  for (int i = 0; i < 8; i++){
    float4 r = *(const float4*)(A + t*RS + 4*i);
    vv[4*i] = r.x; vv[4*i+1] = r.y; vv[4*i+2] = r.z; vv[4*i+3] = r.w;
  }
  float mu = 0.f;
  #pragma unroll
  for (int c = 0; c < 32; c++) mu += vv[c];
  mu *= (1.f/32.f);
  float var = 0.f;
  #pragma unroll
  for (int c = 0; c < 32; c++){ float d = vv[c]-mu; var += d*d; }
  var *= (1.f/32.f);
  float rs = rsqrtf(var + EPSc);
  u64 xu[16];
  #pragma unroll
  for (int i = 0; i < 16; i++){
    float a0 = (vv[2*i]  -mu)*rs*sg1[2*i]   + sbe1[2*i];
    float a1 = (vv[2*i+1]-mu)*rs*sg1[2*i+1] + sbe1[2*i+1];
    xu[i] = pack2(a0, a1);
  }

  u64 qu[16];
  #pragma unroll
  for (int i = 0; i < 16; i++){
    float a0 = leakyf(dot32s(xu, sWq + (2*i  )*32) + sbq[2*i  ]) * SCALEc;
    float a1 = leakyf(dot32s(xu, sWq + (2*i+1)*32) + sbq[2*i+1]) * SCALEc;
    qu[i] = pack2(a0, a1);
  }
  #pragma unroll 2
  for (int j = 0; j < 32; j += 4){
    float a0 = leakyf(dot32s(xu, sWkv + (j  )*32) + sbkv[j  ]);
    float a1 = leakyf(dot32s(xu, sWkv + (j+1)*32) + sbkv[j+1]);
    float a2 = leakyf(dot32s(xu, sWkv + (j+2)*32) + sbkv[j+2]);
    float a3 = leakyf(dot32s(xu, sWkv + (j+3)*32) + sbkv[j+3]);
    *(float4*)(Bb + t*RS + j) = make_float4(a0, a1, a2, a3);
  }
  #pragma unroll 2
  for (int j = 0; j < 32; j += 4){
    float a0 = leakyf(dot32s(xu, sWkv + (32+j  )*32) + sbkv[32+j  ]);
    float a1 = leakyf(dot32s(xu, sWkv + (32+j+1)*32) + sbkv[32+j+1]);
    float a2 = leakyf(dot32s(xu, sWkv + (32+j+2)*32) + sbkv[32+j+2]);
    float a3 = leakyf(dot32s(xu, sWkv + (32+j+3)*32) + sbkv[32+j+3]);
    *(float4*)(A + t*RS + j) = make_float4(a0, a1, a2, a3);
  }
  __syncthreads();

  float s[64];
  float mx = -3.0e38f;
  #pragma unroll
  for (int m = 0; m < 64; m++){
    float sc = dot32s(qu, Bb + m*RS) + sbt[bbias - ((m&7)*15 + (m>>3))];
    s[m] = sc; mx = fmaxf(mx, sc);
  }
  __syncthreads();

  #pragma unroll
  for (int i = 0; i < 8; i++){
    int q = tid + i*256; int gg = q>>9; int tt = (q>>3)&63; int j4 = q&7;
    int w = blockIdx.x*4 + gg; int bb = w>>12, rem = w&4095, wy = rem>>6, wx = rem&63;
    size_t tok = (size_t)bb*262144 + (size_t)(wy*8 + (tt>>3))*512 + wx*8 + (tt&7);
    *(float4*)(rg + gg*4608 + 2304 + tt*RS + j4*4) = *(const float4*)(x + tok*32 + j4*4);
  }

  float l = 0.f;
  #pragma unroll
  for (int m = 0; m < 64; m++){ float p = __expf(s[m]-mx); l += p; s[m] = p; }

  u64 Ou[16];
  #pragma unroll
  for (int i = 0; i < 16; i++) Ou[i] = 0ULL;
  #pragma unroll
  for (int m = 0; m < 64; m++){
    u64 pp = pack2(s[m], s[m]);
    const ulonglong2* vp = (const ulonglong2*)(A + m*RS);
    #pragma unroll
    for (int i = 0; i < 8; i++){
      ulonglong2 vq = vp[i];
      Ou[2*i]   = ffma2(pp, vq.x, Ou[2*i]);
      Ou[2*i+1] = ffma2(pp, vq.y, Ou[2*i+1]);
    }
  }
  {
    float linv = 1.f / l;
    u64 li = pack2(linv, linv);
    #pragma unroll
    for (int i = 0; i < 16; i++) Ou[i] = fmul2(Ou[i], li);
  }
  __syncthreads();

  float x2r[32];
  #pragma unroll 2
  for (int j = 0; j < 32; j++) x2r[j] = dot32s(Ou, sWp + j*32) + sbp[j];
  #pragma unroll
  for (int i = 0; i < 8; i++){
    float4 r = *(const float4*)(Bb + t*RS + 4*i);
    x2r[4*i] += r.x; x2r[4*i+1] += r.y; x2r[4*i+2] += r.z; x2r[4*i+3] += r.w;
  }
  #pragma unroll
  for (int i = 0; i < 8; i++)
    *(float4*)(A + t*RS + 4*i) = make_float4(x2r[4*i], x2r[4*i+1], x2r[4*i+2], x2r[4*i+3]);

  mu = 0.f;
  #pragma unroll
  for (int c = 0; c < 32; c++) mu += x2r[c];
  mu *= (1.f/32.f);
  var = 0.f;
  #pragma unroll
  for (int c = 0; c < 32; c++){ float d = x2r[c]-mu; var += d*d; }
  var *= (1.f/32.f);
  rs = rsqrtf(var + EPSc);
  u64 yu[16];
  #pragma unroll
  for (int i = 0; i < 16; i++){
    float a0 = (x2r[2*i]  -mu)*rs*sg2[2*i]   + sbe2[2*i];
    float a1 = (x2r[2*i+1]-mu)*rs*sg2[2*i+1] + sbe2[2*i+1];
    yu[i] = pack2(a0, a1);
  }
  __syncthreads();

  #pragma unroll
  for (int i = 0; i < 8; i++){
    int q = tid + i*256; int gg = q>>9; int tt = (q>>3)&63; int j4 = q&7;
    int w = blockIdx.x*4 + gg; int bb = w>>12, rem = w&4095, wy = rem>>6, wx = rem&63;
    size_t tok = (size_t)bb*262144 + (size_t)(wy*8 + (tt>>3))*512 + wx*8 + (tt&7);
    *(float4*)(g_x2 + tok*32 + j4*4) = *(const float4*)(rg + gg*4608 + tt*RS + j4*4);
  }
  __syncthreads();

  #pragma unroll 1
  for (int qt = 0; qt < 4; qt++){
    float hq[32];
    #pragma unroll 2
    for (int jj = 0; jj < 32; jj += 4){
      int j = qt*32 + jj;
      hq[jj  ] = geluf(dot32s(yu, sW1 + (j  )*32) + sb1[j  ]);
      hq[jj+1] = geluf(dot32s(yu, sW1 + (j+1)*32) + sb1[j+1]);
      hq[jj+2] = geluf(dot32s(yu, sW1 + (j+2)*32) + sb1[j+2]);
      hq[jj+3] = geluf(dot32s(yu, sW1 + (j+3)*32) + sb1[j+3]);
    }
    #pragma unroll
    for (int i = 0; i < 8; i++)
      *(float4*)(A + t*RS + 4*i) = make_float4(hq[4*i], hq[4*i+1], hq[4*i+2], hq[4*i+3]);
    __syncthreads();
    #pragma unroll
    for (int i = 0; i < 8; i++){
      int q = tid + i*256; int gg = q>>9; int tt = (q>>3)&63; int j4 = q&7;
      int w = blockIdx.x*4 + gg; int bb = w>>12, rem = w&4095, wy = rem>>6, wx = rem&63;
      size_t tok = (size_t)bb*262144 + (size_t)(wy*8 + (tt>>3))*512 + wx*8 + (tt&7);
      *(float4*)(g_h + tok*128 + qt*32 + j4*4) = *(const float4*)(rg + gg*4608 + tt*RS + j4*4);
    }
    __syncthreads();
  }
}

// ======================= K2 v2 =======================
// warp = channel-group (gq = warp&3), lane = pixel. Conv weights + W2 rows are
// warp-uniform smem broadcasts; conv output h stays in registers into the GEMM.
// Partial-sum buffer (64 x 132) aliases the halo tile.
constexpr int PST = 164;
constexpr int K2_SMF = 5768 + 100*PST;   // 22168 floats = 88,672 B

__global__ void __launch_bounds__(256, 2) k2_leff(
    const float* __restrict__ dwk, const float* __restrict__ dwb,
    const float* __restrict__ W2,  const float* __restrict__ b2m,
    float* __restrict__ out)
{
  extern __shared__ float sm[];
  float* sW2  = sm;            // [128 k][32 c]
  float* sdw  = sm + 4096;     // [9 tap][4 grp x 40] stride 168
  float* sdwb = sm + 5608;     // 128
  float* sb2  = sm + 5736;     // 32
  float* st   = sm + 5768;     // 100 x 164 (halo); later aliased as partial[64 x 132]

  const int tid = threadIdx.x;
  for (int i = tid; i < 4096; i += 256) sW2[i] = W2[i];
  for (int i = tid; i < 1152; i += 256){
    int tap = i >> 7, c = i & 127;
    sdw[tap*168 + 40*(c>>5) + (c&31)] = dwk[i];
  }
  if (tid < 128) sdwb[tid] = dwb[tid];
  if (tid < 32)  sb2[tid]  = b2m[tid];

  const int blk = blockIdx.x, b = blk >> 12, rem = blk & 4095;
  const int y0 = (rem >> 6)*8, x0 = (rem & 63)*8;

  // stage halo: warp per pixel vector, coalesced 512B
  const int wid = tid >> 5, lane = tid & 31;
  {
    const int coff = 40*(lane>>3) + 4*(lane&7);
    for (int vid = wid; vid < 100; vid += 8){
      int r = vid/10, c = vid - r*10;
      int hy = y0 + r - 1, hx = x0 + c - 1;
      float4 val = make_float4(0.f, 0.f, 0.f, 0.f);
      if ((unsigned)hy < 512u && (unsigned)hx < 512u)
        val = *(const float4*)(g_h + ((size_t)b*262144 + (size_t)hy*512 + hx)*128 + lane*4);
      *(float4*)(st + vid*PST + coff) = val;
    }
  }
  __syncthreads();

  // ---- conv phase: warp = gq, lane = pixel ----
  const int gq = wid & 3;            // channel group 0..3
  const int p  = (wid >> 2)*32 + lane;  // pixel 0..63
  const int py = p >> 3, px = p & 7;
  const int cv = (py+1)*10 + (px+1);
  const int cb = gq*40;              // padded group offset
  const int cw = gq*32;              // dense channel base

  u64 acc[16];
  #pragma unroll
  for (int i = 0; i < 16; i++) acc[i] = pack2(sdwb[cw+2*i], sdwb[cw+2*i+1]);
  #pragma unroll
  for (int ky = 0; ky < 3; ky++){
    #pragma unroll
    for (int kx = 0; kx < 3; kx++){
      const ulonglong2* hp = (const ulonglong2*)(st + (cv + (ky-1)*10 + (kx-1))*PST + cb);
      const ulonglong2* wp = (const ulonglong2*)(sdw + (ky*3+kx)*168 + cb);  // warp-uniform
      #pragma unroll
      for (int i = 0; i < 8; i++){
        ulonglong2 hv = hp[i], wv = wp[i];
        acc[2*i]   = ffma2(hv.x, wv.x, acc[2*i]);
        acc[2*i+1] = ffma2(hv.y, wv.y, acc[2*i+1]);
      }
    }
  }

  float hg[32];
  #pragma unroll
  for (int i = 0; i < 16; i++){
    float2 f = unpack2(acc[i]);
    hg[2*i] = geluf(f.x); hg[2*i+1] = geluf(f.y);
  }
  __syncthreads();   // all conv reads of st complete before aliasing

  // ---- GEMM partials: 32 outputs for this pixel over this gq's 32 k ----
  u64 pacc[16];
  #pragma unroll
  for (int i = 0; i < 16; i++) pacc[i] = 0ULL;
  #pragma unroll 8
  for (int j = 0; j < 32; j++){
    u64 hh = pack2(hg[j], hg[j]);
    const ulonglong2* wr = (const ulonglong2*)(sW2 + (cw + j)*32);  // warp-uniform
    #pragma unroll
    for (int i = 0; i < 8; i++){
      ulonglong2 wv = wr[i];
      pacc[2*i]   = ffma2(hh, wv.x, pacc[2*i]);
      pacc[2*i+1] = ffma2(hh, wv.y, pacc[2*i+1]);
    }
  }
  // write partials to aliased buffer: part[p][gq*32 + c], row stride 132
  {
    float* prow = st + p*132 + gq*32;
    #pragma unroll
    for (int i = 0; i < 8; i++){
      float2 f0 = unpack2(pacc[2*i]), f1 = unpack2(pacc[2*i+1]);
      *(float4*)(prow + 4*i) = make_float4(f0.x, f0.y, f1.x, f1.y);
    }
  }
  __syncthreads();

  // ---- reduce 4 partials + bias + residual, original (p,gq) mapping ----
  const int p3 = tid >> 2, g3 = tid & 3, c0 = g3*8;
  float o[8];
  #pragma unroll
  for (int i = 0; i < 8; i++) o[i] = sb2[c0+i];
  #pragma unroll
  for (int gp = 0; gp < 4; gp++){
    const float* pr = st + p3*132 + gp*32 + c0;
    float4 a = *(const float4*)(pr);
    float4 bq4 = *(const float4*)(pr + 4);
    o[0]+=a.x; o[1]+=a.y; o[2]+=a.z; o[3]+=a.w;
    o[4]+=bq4.x; o[5]+=bq4.y; o[6]+=bq4.z; o[7]+=bq4.w;
  }
  const int yy = y0 + (p3>>3), xx = x0 + (p3&7);
  const size_t pbase = ((size_t)b*262144 + (size_t)yy*512 + xx)*32 + c0;
  float4 xa = *(const float4*)(g_x2 + pbase);
  float4 xb = *(const float4*)(g_x2 + pbase + 4);
  *(float4*)(out + pbase)     = make_float4(o[0]+xa.x, o[1]+xa.y, o[2]+xa.z, o[3]+xa.w);
  *(float4*)(out + pbase + 4) = make_float4(o[4]+xb.x, o[5]+xb.y, o[6]+xb.z, o[7]+xb.w);
}

// ======================= launch =======================
extern "C" void kernel_launch(void* const* d_in, const int* in_sizes, int n_in,
                              void* d_out, int out_size)
{
  (void)in_sizes; (void)n_in; (void)out_size;
  const float* x    = (const float*)d_in[0];
  const float* g1   = (const float*)d_in[1];
  const float* be1  = (const float*)d_in[2];
  const float* Wq   = (const float*)d_in[3];
  const float* bq   = (const float*)d_in[4];
  const float* Wkv  = (const float*)d_in[5];
  const float* bkv  = (const float*)d_in[6];
  const float* btab = (const float*)d_in[7];
  const float* Wp   = (const float*)d_in[8];
  const float* bp   = (const float*)d_in[9];
  const float* g2   = (const float*)d_in[10];
  const float* be2  = (const float*)d_in[11];
  const float* W1   = (const float*)d_in[12];
  const float* b1m  = (const float*)d_in[13];
  const float* dwk  = (const float*)d_in[14];
  const float* dwb  = (const float*)d_in[15];
  const float* W2   = (const float*)d_in[16];
  const float* b2m  = (const float*)d_in[17];
  float* out = (float*)d_out;

  cudaFuncSetAttribute(k1_attn, cudaFuncAttributeMaxDynamicSharedMemorySize, K1_SMF*4);
  cudaFuncSetAttribute(k2_leff, cudaFuncAttributeMaxDynamicSharedMemorySize, K2_SMF*4);

  k1_attn<<<2048, 256, K1_SMF*4>>>(x, g1, be1, Wq, bq, Wkv, bkv, btab, Wp, bp, g2, be2, W1, b1m);
  k2_leff<<<8192, 256, K2_SMF*4>>>(dwk, dwb, W2, b2m, out);
}